// round 4
// baseline (speedup 1.0000x reference)
#include <cuda_runtime.h>
#include <math.h>

#define NN   50000
#define EE   400000
#define FULLM 0xffffffffu
#define SCAT_B 1563
#define NODE_B 592

typedef unsigned long long u64;

// ---------------- device scratch ----------------
__device__ __align__(16) float g_Q[NN * 128];
__device__ __align__(16) float g_K[NN * 128];
__device__ __align__(16) float g_agg[NN * 128];
__device__ __align__(16) float g_QW[(size_t)NN * 512];  // qef(256) | qt(256) per node
__device__ __align__(16) float g_WqT[64 * 128];
__device__ __align__(16) float g_WkTm[64 * 128];
__device__ __align__(16) float g_W1T[192 * 512];
__device__ __align__(16) float g_qc[128];
__device__ int g_cnt[NN];          // zero-init; scan resets each call
__device__ int g_off[NN + 1];
__device__ int g_cur[NN];
__device__ int g_eidx[EE];

// ---------------- f32x2 helpers ----------------
__device__ __forceinline__ u64 pk2(float lo, float hi) {
    u64 r; asm("mov.b64 %0, {%1, %2};" : "=l"(r) : "f"(lo), "f"(hi)); return r;
}
__device__ __forceinline__ void fma2(u64& d, u64 a, u64 b) {
    asm("fma.rn.f32x2 %0, %1, %2, %0;" : "+l"(d) : "l"(a), "l"(b));
}
__device__ __forceinline__ float2 upk2(u64 v) {
    float lo, hi; asm("mov.b64 {%0, %1}, %2;" : "=f"(lo), "=f"(hi) : "l"(v));
    return make_float2(lo, hi);
}

// ---------------- launch 0: prep + count (cnt zeroed by previous scan) ----------------
__global__ void k_prep(const float* __restrict__ Wq, const float* __restrict__ Wk,
                       const float* __restrict__ W1, const float* __restrict__ time_b,
                       const int* __restrict__ dst) {
    int i = blockIdx.x * blockDim.x + threadIdx.x;
    int gsz = gridDim.x * blockDim.x;
    if (i < 192 * 512) { int k = i / 512, j = i % 512; g_W1T[i] = W1[j * 192 + k]; }
    if (i < 64 * 128) {
        int r = i / 128, j = i % 128;
        g_WkTm[i] = Wk[j * 128 + r];
        g_WqT[i]  = Wq[j * 96 + r];
    }
    if (i < 128) {
        float s = 0.f;
        for (int t = 0; t < 32; t++) s += Wq[i * 96 + 64 + t] * cosf(__ldg(time_b + t));
        g_qc[i] = s;
    }
    for (int e = i; e < EE; e += gsz) atomicAdd(&g_cnt[dst[e]], 1);
}

// ---------------- launch 1: scan (also resets cnt for next call) ----------------
__global__ void k_scan() {
    __shared__ int ss[1024];
    int t = threadIdx.x;
    const int CH = (NN + 1023) / 1024;
    int b = t * CH, s = 0;
    for (int i = 0; i < CH; i++) { int idx = b + i; if (idx < NN) s += g_cnt[idx]; }
    ss[t] = s;
    __syncthreads();
    for (int o = 1; o < 1024; o <<= 1) {
        int v = (t >= o) ? ss[t - o] : 0;
        __syncthreads();
        ss[t] += v;
        __syncthreads();
    }
    int pre = t ? ss[t - 1] : 0;
    for (int i = 0; i < CH; i++) {
        int idx = b + i;
        if (idx < NN) {
            g_off[idx] = pre;
            g_cur[idx] = pre;
            pre += g_cnt[idx];
            g_cnt[idx] = 0;          // reset for next graph replay
        }
    }
    if (t == 1023) g_off[NN] = ss[1023];
}

// ---------------- launch 2: scatter (blocks<SCAT_B) + node proj + qw (rest) ----------------
__global__ __launch_bounds__(256) void k_scatnode(const int* __restrict__ dst,
                                                  const float* __restrict__ memory,
                                                  const float* __restrict__ Wk) {
    if (blockIdx.x < SCAT_B) {
        int e = blockIdx.x * 256 + threadIdx.x;
        if (e < EE) { int p = atomicAdd(&g_cur[dst[e]], 1); g_eidx[p] = e; }
        return;
    }
    extern __shared__ float sm[];
    float* sWq  = sm;            // 8192
    float* sWkm = sm + 8192;     // 8192
    float* sWef = sm + 16384;    // 4096
    float* sWt  = sm + 20480;    // 4096
    int tid = threadIdx.x;
    for (int i = tid; i < 8192; i += 256) { sWq[i] = g_WqT[i]; sWkm[i] = g_WkTm[i]; }
    for (int i = tid; i < 4096; i += 256) {
        int j = i >> 5, f = i & 31;
        sWef[i] = Wk[j * 128 + 64 + f];
        sWt[i]  = Wk[j * 128 + 96 + f];
    }
    __syncthreads();
    int l = tid & 31, w = tid >> 5;
    int h = l >> 2, sub = l & 3;
    int warp = (blockIdx.x - SCAT_B) * 8 + w, stride = NODE_B * 8;
    for (int node = warp; node < NN; node += stride) {
        float2 m2 = *(const float2*)(memory + node * 64 + 2 * l);
        ulonglong2 qc2 = *(const ulonglong2*)(g_qc + 4 * l);
        u64 aQ0 = qc2.x, aQ1 = qc2.y, aK0 = 0ULL, aK1 = 0ULL;
#pragma unroll 8
        for (int i = 0; i < 32; i++) {
            float va = __shfl_sync(FULLM, m2.x, i);
            float vb = __shfl_sync(FULLM, m2.y, i);
            u64 pa = pk2(va, va), pb = pk2(vb, vb);
            ulonglong2 qa = *(const ulonglong2*)(sWq + (2 * i) * 128 + 4 * l);
            ulonglong2 qb = *(const ulonglong2*)(sWq + (2 * i + 1) * 128 + 4 * l);
            ulonglong2 ka = *(const ulonglong2*)(sWkm + (2 * i) * 128 + 4 * l);
            ulonglong2 kb = *(const ulonglong2*)(sWkm + (2 * i + 1) * 128 + 4 * l);
            fma2(aQ0, pa, qa.x); fma2(aQ1, pa, qa.y);
            fma2(aQ0, pb, qb.x); fma2(aQ1, pb, qb.y);
            fma2(aK0, pa, ka.x); fma2(aK1, pa, ka.y);
            fma2(aK0, pb, kb.x); fma2(aK1, pb, kb.y);
        }
        *(ulonglong2*)(g_Q + node * 128 + 4 * l) = make_ulonglong2(aQ0, aQ1);
        *(ulonglong2*)(g_K + node * 128 + 4 * l) = make_ulonglong2(aK0, aK1);
        // qef/qt from register Q
        float2 qa = upk2(aQ0), qb = upk2(aQ1);
        float qv[4] = {qa.x, qa.y, qb.x, qb.y};
        float qef[8], qt[8];
#pragma unroll
        for (int ff = 0; ff < 8; ff++) { qef[ff] = 0.f; qt[ff] = 0.f; }
#pragma unroll
        for (int d = 0; d < 16; d++) {
            int srcl = (l & ~3) | (d >> 2);
            float qd = __shfl_sync(FULLM, qv[d & 3], srcl);
            const float* wr = sWef + (h * 16 + d) * 32 + sub * 8;
            const float* tr = sWt  + (h * 16 + d) * 32 + sub * 8;
            float4 wa = *(const float4*)wr, wb = *(const float4*)(wr + 4);
            float4 ta = *(const float4*)tr, tb4 = *(const float4*)(tr + 4);
            qef[0] = fmaf(qd, wa.x, qef[0]); qef[1] = fmaf(qd, wa.y, qef[1]);
            qef[2] = fmaf(qd, wa.z, qef[2]); qef[3] = fmaf(qd, wa.w, qef[3]);
            qef[4] = fmaf(qd, wb.x, qef[4]); qef[5] = fmaf(qd, wb.y, qef[5]);
            qef[6] = fmaf(qd, wb.z, qef[6]); qef[7] = fmaf(qd, wb.w, qef[7]);
            qt[0] = fmaf(qd, ta.x, qt[0]); qt[1] = fmaf(qd, ta.y, qt[1]);
            qt[2] = fmaf(qd, ta.z, qt[2]); qt[3] = fmaf(qd, ta.w, qt[3]);
            qt[4] = fmaf(qd, tb4.x, qt[4]); qt[5] = fmaf(qd, tb4.y, qt[5]);
            qt[6] = fmaf(qd, tb4.z, qt[6]); qt[7] = fmaf(qd, tb4.w, qt[7]);
        }
        float* qwp = g_QW + (size_t)node * 512 + h * 32 + sub * 8;
        *(float4*)qwp = make_float4(qef[0], qef[1], qef[2], qef[3]);
        *(float4*)(qwp + 4) = make_float4(qef[4], qef[5], qef[6], qef[7]);
        *(float4*)(qwp + 256) = make_float4(qt[0], qt[1], qt[2], qt[3]);
        *(float4*)(qwp + 260) = make_float4(qt[4], qt[5], qt[6], qt[7]);
    }
}

// ---------------- launch 3: edge pass (PROFILED) ----------------
__global__ __launch_bounds__(256) void k_edge(const int* __restrict__ src,
                                              const float* __restrict__ ts,
                                              const float* __restrict__ efeats,
                                              const float* __restrict__ ets,
                                              const float* __restrict__ time_w,
                                              const float* __restrict__ time_b,
                                              const float* __restrict__ Wk) {
    extern __shared__ float sm[];
    float* sWef = sm;            // 4096: [j][f]
    float* sWt  = sm + 4096;     // 4096
    float* sAll = sm + 8192;     // 8 warps * 256
    int tid = threadIdx.x;
    for (int i = tid; i < 4096; i += 256) {
        int j = i >> 5, f = i & 31;
        sWef[i] = Wk[j * 128 + 64 + f];
        sWt[i]  = Wk[j * 128 + 96 + f];
    }
    __syncthreads();
    int l = tid & 31, w = tid >> 5;
    int h = l >> 2, sub = l & 3;
    float* stg = sAll + w * 256;
    float tw = __ldg(time_w + l), tb = __ldg(time_b + l);
    int warp = blockIdx.x * 8 + w, stride = gridDim.x * 8;

    for (int node = warp; node < NN; node += stride) {
        int base = g_off[node];
        int deg = g_off[node + 1] - base;
        float4 q4 = *(const float4*)(g_Q + node * 128 + 4 * l);
        const float* qwp = g_QW + (size_t)node * 512 + h * 32 + sub * 8;
        float4 qe0 = *(const float4*)qwp,         qe1 = *(const float4*)(qwp + 4);
        float4 qt0 = *(const float4*)(qwp + 256), qt1 = *(const float4*)(qwp + 260);

        float4 accA = make_float4(0.f, 0.f, 0.f, 0.f);
        float B[8], C[8];
#pragma unroll
        for (int i = 0; i < 8; i++) { B[i] = 0.f; C[i] = 0.f; }
        float den = 0.f;

        for (int t0 = 0; t0 < deg; t0 += 4) {
            float4 kh[4];
#pragma unroll
            for (int s = 0; s < 4; s++) {
                int t = t0 + s;
                int tc = t < deg ? t : deg - 1;
                int e = g_eidx[base + tc];
                int sn = __ldg(src + e);
                kh[s] = *(const float4*)(g_K + sn * 128 + 4 * l);
                float ef = __ldg(efeats + e * 32 + l);
                float td = __ldg(ets + e) - __ldg(ts + sn);
                stg[s * 64 + l] = ef;
                stg[s * 64 + 32 + l] = cosf(fmaf(td, tw, tb));
            }
            __syncwarp();
#pragma unroll
            for (int s = 0; s < 4; s++) {
                const float* eb = stg + s * 64 + sub * 8;
                const float* cb = eb + 32;
                float4 ea = *(const float4*)eb, e2 = *(const float4*)(eb + 4);
                float4 ca = *(const float4*)cb, c2 = *(const float4*)(cb + 4);
                float p = q4.x * kh[s].x + q4.y * kh[s].y + q4.z * kh[s].z + q4.w * kh[s].w;
                p += qe0.x * ea.x + qe0.y * ea.y + qe0.z * ea.z + qe0.w * ea.w
                   + qe1.x * e2.x + qe1.y * e2.y + qe1.z * e2.z + qe1.w * e2.w
                   + qt0.x * ca.x + qt0.y * ca.y + qt0.z * ca.z + qt0.w * ca.w
                   + qt1.x * c2.x + qt1.y * c2.y + qt1.z * c2.z + qt1.w * c2.w;
                p += __shfl_xor_sync(FULLM, p, 1);
                p += __shfl_xor_sync(FULLM, p, 2);
                float eh = (t0 + s < deg) ? expf(p) : 0.f;
                den += eh;
                accA.x = fmaf(eh, kh[s].x, accA.x);
                accA.y = fmaf(eh, kh[s].y, accA.y);
                accA.z = fmaf(eh, kh[s].z, accA.z);
                accA.w = fmaf(eh, kh[s].w, accA.w);
                B[0] = fmaf(eh, ea.x, B[0]); B[1] = fmaf(eh, ea.y, B[1]);
                B[2] = fmaf(eh, ea.z, B[2]); B[3] = fmaf(eh, ea.w, B[3]);
                B[4] = fmaf(eh, e2.x, B[4]); B[5] = fmaf(eh, e2.y, B[5]);
                B[6] = fmaf(eh, e2.z, B[6]); B[7] = fmaf(eh, e2.w, B[7]);
                C[0] = fmaf(eh, ca.x, C[0]); C[1] = fmaf(eh, ca.y, C[1]);
                C[2] = fmaf(eh, ca.z, C[2]); C[3] = fmaf(eh, ca.w, C[3]);
                C[4] = fmaf(eh, c2.x, C[4]); C[5] = fmaf(eh, c2.y, C[5]);
                C[6] = fmaf(eh, c2.z, C[6]); C[7] = fmaf(eh, c2.w, C[7]);
            }
            __syncwarp();
        }

        float inv = 1.f / (den * 4.f);  // includes 1/sqrt(16)
#pragma unroll
        for (int i = 0; i < 8; i++) { B[i] *= inv; C[i] *= inv; }
        float a0 = accA.x * inv, a1 = accA.y * inv, a2 = accA.z * inv, a3 = accA.w * inv;

        // epilogue: j = 4l..4l+3 (own head), broadcast B/C octets within head group
#pragma unroll
        for (int o = 0; o < 4; o++) {
            int srcl = (l & ~3) | o;
            float bb[8], cc[8];
#pragma unroll
            for (int i = 0; i < 8; i++) {
                bb[i] = __shfl_sync(FULLM, B[i], srcl);
                cc[i] = __shfl_sync(FULLM, C[i], srcl);
            }
#pragma unroll
            for (int jj = 0; jj < 4; jj++) {
                int j = 4 * l + jj;
                const float* wr = sWef + j * 32 + o * 8;
                const float* tr = sWt + j * 32 + o * 8;
                float4 wa = *(const float4*)wr, wb = *(const float4*)(wr + 4);
                float4 ta = *(const float4*)tr, tb4 = *(const float4*)(tr + 4);
                float add = bb[0] * wa.x + bb[1] * wa.y + bb[2] * wa.z + bb[3] * wa.w
                          + bb[4] * wb.x + bb[5] * wb.y + bb[6] * wb.z + bb[7] * wb.w
                          + cc[0] * ta.x + cc[1] * ta.y + cc[2] * ta.z + cc[3] * ta.w
                          + cc[4] * tb4.x + cc[5] * tb4.y + cc[6] * tb4.z + cc[7] * tb4.w;
                if (jj == 0) a0 += add; else if (jj == 1) a1 += add;
                else if (jj == 2) a2 += add; else a3 += add;
            }
        }
        *(float4*)(g_agg + node * 128 + 4 * l) = make_float4(a0, a1, a2, a3);
    }
}

// ---------------- launch 4: merge MLP (f32x2, X duplicated once, W natural pairs) ----------------
__global__ __launch_bounds__(512) void k_merge(const float* __restrict__ memory,
                                               const float* __restrict__ b1,
                                               const float* __restrict__ W2,
                                               const float* __restrict__ b2,
                                               float* __restrict__ out) {
    extern __shared__ char smc[];
    u64* sX2 = (u64*)smc;                    // [192][32] dup pairs = 49152 B
    float* sU = (float*)(smc + 49152);       // [8][512] = 16384 B
    int tid = threadIdx.x;
    int n0 = blockIdx.x * 32;

    for (int idx = tid; idx < 32 * 192; idx += 512) {
        int n = idx & 31, k = idx >> 5;
        int node = n0 + n;
        float v = 0.f;
        if (node < NN) v = (k < 128) ? g_agg[node * 128 + k] : __ldg(memory + node * 64 + (k - 128));
        sX2[k * 32 + n] = pk2(v, v);
    }

    int cg = tid & 127, ng = tid >> 7;
    int j0 = cg * 4, m0 = ng * 8;
    u64 acc[8][2];
#pragma unroll
    for (int m = 0; m < 8; m++) { acc[m][0] = 0ULL; acc[m][1] = 0ULL; }

    for (int c = 0; c < 24; c++) {
        __syncthreads();
        for (int idx = tid; idx < 4096; idx += 512) sU[idx] = g_W1T[c * 4096 + idx];
        __syncthreads();
#pragma unroll
        for (int kk = 0; kk < 8; kk++) {
            int k = c * 8 + kk;
            const u64* xp = sX2 + k * 32 + m0;
            ulonglong2 xA = *(const ulonglong2*)xp;
            ulonglong2 xB = *(const ulonglong2*)(xp + 2);
            ulonglong2 xC = *(const ulonglong2*)(xp + 4);
            ulonglong2 xD = *(const ulonglong2*)(xp + 6);
            ulonglong2 wv = *(const ulonglong2*)(sU + kk * 512 + j0);
            fma2(acc[0][0], xA.x, wv.x); fma2(acc[0][1], xA.x, wv.y);
            fma2(acc[1][0], xA.y, wv.x); fma2(acc[1][1], xA.y, wv.y);
            fma2(acc[2][0], xB.x, wv.x); fma2(acc[2][1], xB.x, wv.y);
            fma2(acc[3][0], xB.y, wv.x); fma2(acc[3][1], xB.y, wv.y);
            fma2(acc[4][0], xC.x, wv.x); fma2(acc[4][1], xC.x, wv.y);
            fma2(acc[5][0], xC.y, wv.x); fma2(acc[5][1], xC.y, wv.y);
            fma2(acc[6][0], xD.x, wv.x); fma2(acc[6][1], xD.x, wv.y);
            fma2(acc[7][0], xD.y, wv.x); fma2(acc[7][1], xD.y, wv.y);
        }
    }

    float4 bb4 = *(const float4*)(b1 + j0);
    float hv[8][4];
#pragma unroll
    for (int m = 0; m < 8; m++) {
        float2 p0 = upk2(acc[m][0]), p1 = upk2(acc[m][1]);
        float v0 = p0.x + bb4.x, v1 = p0.y + bb4.y, v2 = p1.x + bb4.z, v3 = p1.y + bb4.w;
        hv[m][0] = v0 > 0.f ? v0 : 0.f;
        hv[m][1] = v1 > 0.f ? v1 : 0.f;
        hv[m][2] = v2 > 0.f ? v2 : 0.f;
        hv[m][3] = v3 > 0.f ? v3 : 0.f;
    }

    // second GEMM: out[m][o] = hid[m][:] . W2[o][:]
    int mo_m = tid >> 4, mo_o = tid & 15;
    float* sHc = (float*)smc;                 // [32][132]
    float* sW2c = (float*)(smc + 33792);      // [16][132]
    float oacc = 0.f;
    for (int c2 = 0; c2 < 4; c2++) {
        __syncthreads();
        if ((cg >> 5) == c2) {
            int jj = (cg & 31) * 4;
#pragma unroll
            for (int mi = 0; mi < 8; mi++)
                *(float4*)(sHc + (m0 + mi) * 132 + jj) =
                    make_float4(hv[mi][0], hv[mi][1], hv[mi][2], hv[mi][3]);
        }
        for (int idx = tid; idx < 16 * 128; idx += 512) {
            int o = idx >> 7, jj = idx & 127;
            sW2c[o * 132 + jj] = __ldg(W2 + o * 512 + c2 * 128 + jj);
        }
        __syncthreads();
#pragma unroll 8
        for (int j4 = 0; j4 < 32; j4++) {
            float4 h4 = *(const float4*)(sHc + mo_m * 132 + 4 * j4);
            float4 w4 = *(const float4*)(sW2c + mo_o * 132 + 4 * j4);
            oacc += h4.x * w4.x + h4.y * w4.y + h4.z * w4.z + h4.w * w4.w;
        }
    }
    int node = n0 + mo_m;
    if (node < NN) out[node * 16 + mo_o] = oacc + __ldg(b2 + mo_o);
}

// ---------------- launch ----------------
extern "C" void kernel_launch(void* const* d_in, const int* in_sizes, int n_in,
                              void* d_out, int out_size) {
    const int*   src    = (const int*)d_in[0];
    const int*   dst    = (const int*)d_in[1];
    const float* memory = (const float*)d_in[2];
    const float* ts     = (const float*)d_in[3];
    const float* efeats = (const float*)d_in[4];
    const float* ets    = (const float*)d_in[5];
    const float* Wq     = (const float*)d_in[6];
    const float* Wk     = (const float*)d_in[7];
    const float* W1     = (const float*)d_in[8];
    const float* b1     = (const float*)d_in[9];
    const float* W2     = (const float*)d_in[10];
    const float* b2     = (const float*)d_in[11];
    const float* time_w = (const float*)d_in[12];
    const float* time_b = (const float*)d_in[13];
    float* out = (float*)d_out;

    cudaFuncSetAttribute(k_scatnode, cudaFuncAttributeMaxDynamicSharedMemorySize, 98304);
    cudaFuncSetAttribute(k_edge,     cudaFuncAttributeMaxDynamicSharedMemorySize, 49152);
    cudaFuncSetAttribute(k_merge,    cudaFuncAttributeMaxDynamicSharedMemorySize, 65536);

    k_prep<<<384, 256>>>(Wq, Wk, W1, time_b, dst);
    k_scan<<<1, 1024>>>();
    k_scatnode<<<SCAT_B + NODE_B, 256, 98304>>>(dst, memory, Wk);
    k_edge<<<592, 256, 40960>>>(src, ts, efeats, ets, time_w, time_b, Wk);
    k_merge<<<(NN + 31) / 32, 512, 65536>>>(memory, b1, W2, b2, out);
}

// round 6
// speedup vs baseline: 1.4840x; 1.4840x over previous
#include <cuda_runtime.h>
#include <math.h>

#define NN   50000
#define EE   400000
#define FULLM 0xffffffffu
#define SCAT_B 1563
#define NODE_B 592

typedef unsigned long long u64;

__device__ __align__(16) float g_Q[NN * 128];
__device__ __align__(16) float g_K[NN * 128];
__device__ __align__(16) float g_agg[NN * 128];
__device__ __align__(16) float g_QW[(size_t)NN * 512];
__device__ __align__(16) float g_WqT[64 * 128];
__device__ __align__(16) float g_WkTm[64 * 128];
__device__ __align__(16) float g_W1T[192 * 512];
__device__ __align__(16) float g_qc[128];
__device__ int g_cnt[NN];
__device__ int g_off[NN + 1];
__device__ int g_cur[NN];
__device__ int g_eidx[EE];

__device__ __forceinline__ u64 pk2(float lo, float hi) {
    u64 r; asm("mov.b64 %0, {%1, %2};" : "=l"(r) : "f"(lo), "f"(hi)); return r;
}
__device__ __forceinline__ void fma2(u64& d, u64 a, u64 b) {
    asm("fma.rn.f32x2 %0, %1, %2, %0;" : "+l"(d) : "l"(a), "l"(b));
}
__device__ __forceinline__ float2 upk2(u64 v) {
    float lo, hi; asm("mov.b64 {%0, %1}, %2;" : "=f"(lo), "=f"(hi) : "l"(v));
    return make_float2(lo, hi);
}

// ---------------- launch 0: prep + count ----------------
__global__ void k_prep(const float* __restrict__ Wq, const float* __restrict__ Wk,
                       const float* __restrict__ W1, const float* __restrict__ time_b,
                       const int* __restrict__ dst) {
    int i = blockIdx.x * blockDim.x + threadIdx.x;
    int gsz = gridDim.x * blockDim.x;
    if (i < 192 * 512) { int k = i / 512, j = i % 512; g_W1T[i] = W1[j * 192 + k]; }
    if (i < 64 * 128) {
        int r = i / 128, j = i % 128;
        g_WkTm[i] = Wk[j * 128 + r];
        g_WqT[i]  = Wq[j * 96 + r];
    }
    if (i < 128) {
        float s = 0.f;
        for (int t = 0; t < 32; t++) s += Wq[i * 96 + 64 + t] * cosf(__ldg(time_b + t));
        g_qc[i] = s;
    }
    for (int e = i; e < EE; e += gsz) atomicAdd(&g_cnt[dst[e]], 1);
}

// ---------------- launch 1: scan (resets cnt) ----------------
__global__ void k_scan() {
    __shared__ int ss[1024];
    int t = threadIdx.x;
    const int CH = (NN + 1023) / 1024;
    int b = t * CH, s = 0;
    for (int i = 0; i < CH; i++) { int idx = b + i; if (idx < NN) s += g_cnt[idx]; }
    ss[t] = s;
    __syncthreads();
    for (int o = 1; o < 1024; o <<= 1) {
        int v = (t >= o) ? ss[t - o] : 0;
        __syncthreads();
        ss[t] += v;
        __syncthreads();
    }
    int pre = t ? ss[t - 1] : 0;
    for (int i = 0; i < CH; i++) {
        int idx = b + i;
        if (idx < NN) {
            g_off[idx] = pre; g_cur[idx] = pre;
            pre += g_cnt[idx];
            g_cnt[idx] = 0;
        }
    }
    if (t == 1023) g_off[NN] = ss[1023];
}

// ---------------- launch 2: scatter + node proj + qw ----------------
__global__ __launch_bounds__(256) void k_scatnode(const int* __restrict__ dst,
                                                  const float* __restrict__ memory,
                                                  const float* __restrict__ Wk) {
    if (blockIdx.x < SCAT_B) {
        int e = blockIdx.x * 256 + threadIdx.x;
        if (e < EE) { int p = atomicAdd(&g_cur[dst[e]], 1); g_eidx[p] = e; }
        return;
    }
    extern __shared__ float sm[];
    float* sWq  = sm;             // 8192
    float* sWkm = sm + 8192;      // 8192
    float* sWef = sm + 16384;     // 128*36 = 4608 (padded, 16B-aligned rows)
    float* sWt  = sm + 20992;     // 4608
    int tid = threadIdx.x;
    for (int i = tid; i < 8192; i += 256) { sWq[i] = g_WqT[i]; sWkm[i] = g_WkTm[i]; }
    for (int i = tid; i < 4096; i += 256) {
        int j = i >> 5, f = i & 31;
        sWef[j * 36 + f] = Wk[j * 128 + 64 + f];
        sWt [j * 36 + f] = Wk[j * 128 + 96 + f];
    }
    __syncthreads();
    int l = tid & 31, w = tid >> 5;
    int h = l >> 2, sub = l & 3;
    int warp = (blockIdx.x - SCAT_B) * 8 + w, stride = NODE_B * 8;
    for (int node = warp; node < NN; node += stride) {
        float2 m2 = *(const float2*)(memory + node * 64 + 2 * l);
        ulonglong2 qc2 = *(const ulonglong2*)(g_qc + 4 * l);
        u64 aQ0 = qc2.x, aQ1 = qc2.y, aK0 = 0ULL, aK1 = 0ULL;
#pragma unroll 8
        for (int i = 0; i < 32; i++) {
            float va = __shfl_sync(FULLM, m2.x, i);
            float vb = __shfl_sync(FULLM, m2.y, i);
            u64 pa = pk2(va, va), pb = pk2(vb, vb);
            ulonglong2 qa = *(const ulonglong2*)(sWq + (2 * i) * 128 + 4 * l);
            ulonglong2 qb = *(const ulonglong2*)(sWq + (2 * i + 1) * 128 + 4 * l);
            ulonglong2 ka = *(const ulonglong2*)(sWkm + (2 * i) * 128 + 4 * l);
            ulonglong2 kb = *(const ulonglong2*)(sWkm + (2 * i + 1) * 128 + 4 * l);
            fma2(aQ0, pa, qa.x); fma2(aQ1, pa, qa.y);
            fma2(aQ0, pb, qb.x); fma2(aQ1, pb, qb.y);
            fma2(aK0, pa, ka.x); fma2(aK1, pa, ka.y);
            fma2(aK0, pb, kb.x); fma2(aK1, pb, kb.y);
        }
        *(ulonglong2*)(g_Q + node * 128 + 4 * l) = make_ulonglong2(aQ0, aQ1);
        *(ulonglong2*)(g_K + node * 128 + 4 * l) = make_ulonglong2(aK0, aK1);
        float2 qa2 = upk2(aQ0), qb2 = upk2(aQ1);
        float qv[4] = {qa2.x, qa2.y, qb2.x, qb2.y};
        float qef[8], qt[8];
#pragma unroll
        for (int ff = 0; ff < 8; ff++) { qef[ff] = 0.f; qt[ff] = 0.f; }
#pragma unroll
        for (int d = 0; d < 16; d++) {
            int srcl = (l & ~3) | (d >> 2);
            float qd = __shfl_sync(FULLM, qv[d & 3], srcl);
            const float* wr = sWef + (h * 16 + d) * 36 + sub * 8;
            const float* tr = sWt  + (h * 16 + d) * 36 + sub * 8;
            float4 wa = *(const float4*)wr, wb = *(const float4*)(wr + 4);
            float4 ta = *(const float4*)tr, tb4 = *(const float4*)(tr + 4);
            qef[0] = fmaf(qd, wa.x, qef[0]); qef[1] = fmaf(qd, wa.y, qef[1]);
            qef[2] = fmaf(qd, wa.z, qef[2]); qef[3] = fmaf(qd, wa.w, qef[3]);
            qef[4] = fmaf(qd, wb.x, qef[4]); qef[5] = fmaf(qd, wb.y, qef[5]);
            qef[6] = fmaf(qd, wb.z, qef[6]); qef[7] = fmaf(qd, wb.w, qef[7]);
            qt[0] = fmaf(qd, ta.x, qt[0]); qt[1] = fmaf(qd, ta.y, qt[1]);
            qt[2] = fmaf(qd, ta.z, qt[2]); qt[3] = fmaf(qd, ta.w, qt[3]);
            qt[4] = fmaf(qd, tb4.x, qt[4]); qt[5] = fmaf(qd, tb4.y, qt[5]);
            qt[6] = fmaf(qd, tb4.z, qt[6]); qt[7] = fmaf(qd, tb4.w, qt[7]);
        }
        float* qwp = g_QW + (size_t)node * 512 + h * 32 + sub * 8;
        *(float4*)qwp = make_float4(qef[0], qef[1], qef[2], qef[3]);
        *(float4*)(qwp + 4) = make_float4(qef[4], qef[5], qef[6], qef[7]);
        *(float4*)(qwp + 256) = make_float4(qt[0], qt[1], qt[2], qt[3]);
        *(float4*)(qwp + 260) = make_float4(qt[4], qt[5], qt[6], qt[7]);
    }
}

// ---------------- launch 3: edge pass (PROFILED), conflict-free epilogue ----------------
__global__ __launch_bounds__(256) void k_edge(const int* __restrict__ src,
                                              const float* __restrict__ ts,
                                              const float* __restrict__ efeats,
                                              const float* __restrict__ ets,
                                              const float* __restrict__ time_w,
                                              const float* __restrict__ time_b,
                                              const float* __restrict__ Wk) {
    extern __shared__ float sm[];
    float* sWef = sm;            // f-major [f][j]: 32*128 = 4096
    float* sWt  = sm + 4096;     // 4096
    float* sAll = sm + 8192;     // 8 warps * 256
    int tid = threadIdx.x;
    for (int i = tid; i < 4096; i += 256) {
        int f = i & 31, j = i >> 5;
        sWef[f * 128 + j] = Wk[j * 128 + 64 + f];
        sWt [f * 128 + j] = Wk[j * 128 + 96 + f];
    }
    __syncthreads();
    int l = tid & 31, w = tid >> 5;
    int sub = l & 3;
    int hb = l & ~3;             // head group base lane
    float* stg = sAll + w * 256;
    float tw = __ldg(time_w + l), tb = __ldg(time_b + l);
    int warp = blockIdx.x * 8 + w, stride = gridDim.x * 8;

    for (int node = warp; node < NN; node += stride) {
        int base = g_off[node];
        int deg = g_off[node + 1] - base;
        float4 q4 = *(const float4*)(g_Q + node * 128 + 4 * l);
        const float* qwp = g_QW + (size_t)node * 512 + (l >> 2) * 32 + sub * 8;
        float4 qe0 = *(const float4*)qwp,         qe1 = *(const float4*)(qwp + 4);
        float4 qt0 = *(const float4*)(qwp + 256), qt1 = *(const float4*)(qwp + 260);

        float4 accA = make_float4(0.f, 0.f, 0.f, 0.f);
        float B[8], C[8];
#pragma unroll
        for (int i = 0; i < 8; i++) { B[i] = 0.f; C[i] = 0.f; }
        float den = 0.f;

        for (int t0 = 0; t0 < deg; t0 += 4) {
            float4 kh[4];
#pragma unroll
            for (int s = 0; s < 4; s++) {
                int t = t0 + s;
                int tc = t < deg ? t : deg - 1;
                int e = g_eidx[base + tc];
                int sn = __ldg(src + e);
                kh[s] = *(const float4*)(g_K + sn * 128 + 4 * l);
                float ef = __ldg(efeats + e * 32 + l);
                float td = __ldg(ets + e) - __ldg(ts + sn);
                stg[s * 64 + l] = ef;
                stg[s * 64 + 32 + l] = cosf(fmaf(td, tw, tb));
            }
            __syncwarp();
#pragma unroll
            for (int s = 0; s < 4; s++) {
                const float* eb = stg + s * 64 + sub * 8;
                const float* cb = eb + 32;
                float4 ea = *(const float4*)eb, e2 = *(const float4*)(eb + 4);
                float4 ca = *(const float4*)cb, c2 = *(const float4*)(cb + 4);
                float p = q4.x * kh[s].x + q4.y * kh[s].y + q4.z * kh[s].z + q4.w * kh[s].w;
                p += qe0.x * ea.x + qe0.y * ea.y + qe0.z * ea.z + qe0.w * ea.w
                   + qe1.x * e2.x + qe1.y * e2.y + qe1.z * e2.z + qe1.w * e2.w
                   + qt0.x * ca.x + qt0.y * ca.y + qt0.z * ca.z + qt0.w * ca.w
                   + qt1.x * c2.x + qt1.y * c2.y + qt1.z * c2.z + qt1.w * c2.w;
                p += __shfl_xor_sync(FULLM, p, 1);
                p += __shfl_xor_sync(FULLM, p, 2);
                float eh = (t0 + s < deg) ? expf(p) : 0.f;
                den += eh;
                accA.x = fmaf(eh, kh[s].x, accA.x);
                accA.y = fmaf(eh, kh[s].y, accA.y);
                accA.z = fmaf(eh, kh[s].z, accA.z);
                accA.w = fmaf(eh, kh[s].w, accA.w);
                B[0] = fmaf(eh, ea.x, B[0]); B[1] = fmaf(eh, ea.y, B[1]);
                B[2] = fmaf(eh, ea.z, B[2]); B[3] = fmaf(eh, ea.w, B[3]);
                B[4] = fmaf(eh, e2.x, B[4]); B[5] = fmaf(eh, e2.y, B[5]);
                B[6] = fmaf(eh, e2.z, B[6]); B[7] = fmaf(eh, e2.w, B[7]);
                C[0] = fmaf(eh, ca.x, C[0]); C[1] = fmaf(eh, ca.y, C[1]);
                C[2] = fmaf(eh, ca.z, C[2]); C[3] = fmaf(eh, ca.w, C[3]);
                C[4] = fmaf(eh, c2.x, C[4]); C[5] = fmaf(eh, c2.y, C[5]);
                C[6] = fmaf(eh, c2.z, C[6]); C[7] = fmaf(eh, c2.w, C[7]);
            }
            __syncwarp();
        }

        float inv = 1.f / (den * 4.f);   // includes 1/sqrt(16)
#pragma unroll
        for (int i = 0; i < 8; i++) { B[i] *= inv; C[i] *= inv; }
        float a0 = accA.x * inv, a1 = accA.y * inv, a2 = accA.z * inv, a3 = accA.w * inv;

        // epilogue: cols j = 4l..4l+3 (head l>>2); f-major weights, conflict-free
#pragma unroll
        for (int g = 0; g < 4; g++) {
#pragma unroll
            for (int i = 0; i < 8; i++) {
                int f = g * 8 + i;
                float bv = __shfl_sync(FULLM, B[i], hb | g);
                float cv = __shfl_sync(FULLM, C[i], hb | g);
                float4 we = *(const float4*)(sWef + f * 128 + 4 * l);
                float4 wt4 = *(const float4*)(sWt + f * 128 + 4 * l);
                a0 = fmaf(bv, we.x, fmaf(cv, wt4.x, a0));
                a1 = fmaf(bv, we.y, fmaf(cv, wt4.y, a1));
                a2 = fmaf(bv, we.z, fmaf(cv, wt4.z, a2));
                a3 = fmaf(bv, we.w, fmaf(cv, wt4.w, a3));
            }
        }
        *(float4*)(g_agg + node * 128 + 4 * l) = make_float4(a0, a1, a2, a3);
    }
}

// ---------------- launch 4: merge MLP (broadcast-X f32x2, natural W col-pairs) ----------------
__global__ __launch_bounds__(512) void k_merge(const float* __restrict__ memory,
                                               const float* __restrict__ b1,
                                               const float* __restrict__ W2,
                                               const float* __restrict__ b2,
                                               float* __restrict__ out) {
    extern __shared__ char smc[];
    float* sX = (float*)smc;                  // [192][36] = 27648 B
    float* sU = (float*)(smc + 27648);        // [8][512] = 16384 B
    int tid = threadIdx.x;
    int n0 = blockIdx.x * 32;

    for (int idx = tid; idx < 32 * 192; idx += 512) {
        int n = idx & 31, k = idx >> 5;
        int node = n0 + n;
        float v = 0.f;
        if (node < NN) v = (k < 128) ? g_agg[node * 128 + k] : __ldg(memory + node * 64 + (k - 128));
        sX[k * 36 + n] = v;
    }

    int cg = tid & 127, ng = tid >> 7;
    int j0 = cg * 4, m0 = ng * 8;
    u64 acc[8][2];
#pragma unroll
    for (int m = 0; m < 8; m++) { acc[m][0] = 0ULL; acc[m][1] = 0ULL; }

    for (int c = 0; c < 24; c++) {
        __syncthreads();
        for (int idx = tid; idx < 4096; idx += 512) sU[idx] = g_W1T[c * 4096 + idx];
        __syncthreads();
#pragma unroll
        for (int kk = 0; kk < 8; kk++) {
            int k = c * 8 + kk;
            float4 xa = *(const float4*)(sX + k * 36 + m0);       // broadcast
            float4 xb = *(const float4*)(sX + k * 36 + m0 + 4);   // broadcast
            ulonglong2 wv = *(const ulonglong2*)(sU + kk * 512 + j0);  // natural pairs
            u64 x0 = pk2(xa.x, xa.x), x1 = pk2(xa.y, xa.y);
            u64 x2 = pk2(xa.z, xa.z), x3 = pk2(xa.w, xa.w);
            u64 x4 = pk2(xb.x, xb.x), x5 = pk2(xb.y, xb.y);
            u64 x6 = pk2(xb.z, xb.z), x7 = pk2(xb.w, xb.w);
            fma2(acc[0][0], x0, wv.x); fma2(acc[0][1], x0, wv.y);
            fma2(acc[1][0], x1, wv.x); fma2(acc[1][1], x1, wv.y);
            fma2(acc[2][0], x2, wv.x); fma2(acc[2][1], x2, wv.y);
            fma2(acc[3][0], x3, wv.x); fma2(acc[3][1], x3, wv.y);
            fma2(acc[4][0], x4, wv.x); fma2(acc[4][1], x4, wv.y);
            fma2(acc[5][0], x5, wv.x); fma2(acc[5][1], x5, wv.y);
            fma2(acc[6][0], x6, wv.x); fma2(acc[6][1], x6, wv.y);
            fma2(acc[7][0], x7, wv.x); fma2(acc[7][1], x7, wv.y);
        }
    }

    float4 bb4 = *(const float4*)(b1 + j0);
    float hv[8][4];
#pragma unroll
    for (int m = 0; m < 8; m++) {
        float2 p0 = upk2(acc[m][0]), p1 = upk2(acc[m][1]);
        float v0 = p0.x + bb4.x, v1 = p0.y + bb4.y, v2 = p1.x + bb4.z, v3 = p1.y + bb4.w;
        hv[m][0] = v0 > 0.f ? v0 : 0.f;
        hv[m][1] = v1 > 0.f ? v1 : 0.f;
        hv[m][2] = v2 > 0.f ? v2 : 0.f;
        hv[m][3] = v3 > 0.f ? v3 : 0.f;
    }

    // second GEMM: out[m][o] = hid[m][:] . W2[o][:]
    int mo_m = tid >> 4, mo_o = tid & 15;
    float* sHc = (float*)smc;                 // [32][132]
    float* sW2c = (float*)(smc + 33792);      // [16][132]
    float oacc = 0.f;
    for (int c2 = 0; c2 < 4; c2++) {
        __syncthreads();
        if ((cg >> 5) == c2) {
            int jj = (cg & 31) * 4;
#pragma unroll
            for (int mi = 0; mi < 8; mi++)
                *(float4*)(sHc + (m0 + mi) * 132 + jj) =
                    make_float4(hv[mi][0], hv[mi][1], hv[mi][2], hv[mi][3]);
        }
        for (int idx = tid; idx < 16 * 128; idx += 512) {
            int o = idx >> 7, jj = idx & 127;
            sW2c[o * 132 + jj] = __ldg(W2 + o * 512 + c2 * 128 + jj);
        }
        __syncthreads();
#pragma unroll 8
        for (int j4 = 0; j4 < 32; j4++) {
            float4 h4 = *(const float4*)(sHc + mo_m * 132 + 4 * j4);
            float4 w4 = *(const float4*)(sW2c + mo_o * 132 + 4 * j4);
            oacc += h4.x * w4.x + h4.y * w4.y + h4.z * w4.z + h4.w * w4.w;
        }
    }
    int node = n0 + mo_m;
    if (node < NN) out[node * 16 + mo_o] = oacc + __ldg(b2 + mo_o);
}

// ---------------- launch ----------------
extern "C" void kernel_launch(void* const* d_in, const int* in_sizes, int n_in,
                              void* d_out, int out_size) {
    const int*   src    = (const int*)d_in[0];
    const int*   dst    = (const int*)d_in[1];
    const float* memory = (const float*)d_in[2];
    const float* ts     = (const float*)d_in[3];
    const float* efeats = (const float*)d_in[4];
    const float* ets    = (const float*)d_in[5];
    const float* Wq     = (const float*)d_in[6];
    const float* Wk     = (const float*)d_in[7];
    const float* W1     = (const float*)d_in[8];
    const float* b1     = (const float*)d_in[9];
    const float* W2     = (const float*)d_in[10];
    const float* b2     = (const float*)d_in[11];
    const float* time_w = (const float*)d_in[12];
    const float* time_b = (const float*)d_in[13];
    float* out = (float*)d_out;

    cudaFuncSetAttribute(k_scatnode, cudaFuncAttributeMaxDynamicSharedMemorySize, 102400);
    cudaFuncSetAttribute(k_edge,     cudaFuncAttributeMaxDynamicSharedMemorySize, 40960);
    cudaFuncSetAttribute(k_merge,    cudaFuncAttributeMaxDynamicSharedMemorySize, 44032);

    k_prep<<<384, 256>>>(Wq, Wk, W1, time_b, dst);
    k_scan<<<1, 1024>>>();
    k_scatnode<<<SCAT_B + NODE_B, 256, 102400>>>(dst, memory, Wk);
    k_edge<<<592, 256, 40960>>>(src, ts, efeats, ets, time_w, time_b, Wk);
    k_merge<<<(NN + 31) / 32, 512, 44032>>>(memory, b1, W2, b2, out);
}